// round 3
// baseline (speedup 1.0000x reference)
#include <cuda_runtime.h>

// ============================================================================
// CustomLinear fused q/k/v projection (f32x2 packed-FMA version)
//   x: (8, 4096, 130) fp32; per token:
//     x1 = x[0:64], s_mid = x[64], x2 = x[65:129], s_last = x[129]
//   q head h<4:  e[65:129] = M_q[h] @ x2 ; e[129] = s_last*bq[h]
//   q head h>=4: e[65]     = s_last*bq[h]
//   k head h<4:  e[65:129] = M_k[h] @ x1 ; e[129] = s_last*bk[h]
//   k head h>=4: e[65]     = s_mid *bk[h]
//   v all h:     e[65:129] = M_v[h] @ x1
//   out = concat(q, k, v), each (8, 4096, 8*130) fp32
// ============================================================================

#define TOK 32   // tokens per CTA
#define TG  8    // tokens per register accumulation group

typedef unsigned long long ull;

// Transposed weights: g_MT[m][j*64 + i] = M_m[i][j], m = 0..3 Mq, 4..7 Mk, 8..15 Mv
__device__ __align__(16) float g_MT[16 * 4096];

__global__ void transpose_kernel(const float* __restrict__ Mq,
                                 const float* __restrict__ Mk,
                                 const float* __restrict__ Mv) {
    int m = blockIdx.x;  // 0..15
    const float* src = (m < 4) ? (Mq + m * 4096)
                     : (m < 8) ? (Mk + (m - 4) * 4096)
                               : (Mv + (m - 8) * 4096);
    float* dst = g_MT + m * 4096;
    for (int idx = threadIdx.x; idx < 4096; idx += blockDim.x) {
        int i = idx >> 6, j = idx & 63;
        dst[j * 64 + i] = src[idx];
    }
}

// packed fp32x2 FMA: d.lo += a.lo*b.lo ; d.hi += a.hi*b.hi   (Blackwell PTX)
__device__ __forceinline__ void fma2(ull& d, ull a, ull b) {
    asm("fma.rn.f32x2 %0, %1, %2, %0;" : "+l"(d) : "l"(a), "l"(b));
}

__device__ __forceinline__ ull dup2(float v) {
    ull r;
    asm("mov.b64 %0, {%1, %1};" : "=l"(r) : "f"(v));
    return r;
}

__global__ void __launch_bounds__(256, 3) qkv_kernel(
    const float* __restrict__ x,
    const float* __restrict__ Bq,
    const float* __restrict__ Bk,
    float* __restrict__ out)
{
    __shared__ __align__(16) ull xd[TOK * 64];   // x slice, each value duplicated {v,v}
    __shared__ float2 xs[TOK];                   // {s_mid, s_last}

    const int  tz = blockIdx.y;                 // 0 = q, 1 = k, 2 = v
    const long g0 = (long)blockIdx.x * TOK;     // first global token of this CTA
    const int  slice_off = (tz == 0) ? 65 : 0;  // q reads x2, k/v read x1

    // Stage x slice for TOK tokens, duplicated for packed broadcast
    for (int idx = threadIdx.x; idx < TOK * 64; idx += 256) {
        int t = idx >> 6, j = idx & 63;
        xd[idx] = dup2(x[(g0 + t) * 130 + slice_off + j]);
    }
    if (threadIdx.x < TOK) {
        int t = threadIdx.x;
        xs[t] = make_float2(x[(g0 + t) * 130 + 64], x[(g0 + t) * 130 + 129]);
    }
    __syncthreads();

    const int w    = threadIdx.x >> 5;
    const int lane = threadIdx.x & 31;
    // out regions: q | k | v, each 8*4096*1040 floats = 17,039,360 float2
    float2* out2 = (float2*)out + (long)tz * 17039360L;

    int h, ngroup, t0_base;
    const float* MT;
    float bh = 0.f, bh4 = 0.f;
    if (tz < 2) {
        h = w >> 1;                       // matvec head 0..3
        int sub = w & 1;
        ngroup = 2;                       // 2 groups of 8 tokens
        t0_base = sub * 16;
        MT = g_MT + ((tz ? 4 : 0) + h) * 4096;
        const float* Bv = tz ? Bk : Bq;
        bh  = Bv[h];
        bh4 = Bv[h + 4];
    } else {
        h = w;                            // v: warp = head, 4 groups of 8 tokens
        ngroup = 4;
        t0_base = 0;
        MT = g_MT + (8 + h) * 4096;
    }

    for (int grp = 0; grp < ngroup; grp++) {
        const int t0 = t0_base + grp * TG;

        // lane computes packed outputs {2*lane, 2*lane+1} for TG tokens
        ull acc[TG];
        #pragma unroll
        for (int t = 0; t < TG; t++) acc[t] = 0ULL;

        #pragma unroll
        for (int jc = 0; jc < 4; jc++) {
            // register-cache M^T chunk: 16 j's x packed output pair (L1-resident)
            ull m[16];
            #pragma unroll
            for (int jj = 0; jj < 16; jj++)
                m[jj] = __ldg((const ull*)(MT + (jc * 16 + jj) * 64) + lane);

            #pragma unroll
            for (int t = 0; t < TG; t++) {
                const ulonglong2* xr =
                    (const ulonglong2*)(xd + (t0 + t) * 64 + jc * 16);
                #pragma unroll
                for (int jj = 0; jj < 16; jj += 2) {
                    ulonglong2 xv = xr[jj >> 1];     // broadcast LDS.128: 2 packed x
                    fma2(acc[t], m[jj    ], xv.x);
                    fma2(acc[t], m[jj + 1], xv.y);
                }
            }
        }

        // Write the full 130-float head block(s) as aligned float2 pairs.
        // Pair p covers slots (2p, 2p+1); payload lives at slots 65..129, so
        // pair 32+l = {out[2l-1], out[2l]} via shfl_up.
        #pragma unroll
        for (int t = 0; t < TG; t++) {
            long   g     = g0 + t0 + t;
            float2* dst  = out2 + g * 520 + h * 65;
            float  s_mid = xs[t0 + t].x, s_last = xs[t0 + t].y;
            float2 a     = *(float2*)&acc[t];        // a.x = out[2l], a.y = out[2l+1]

            dst[lane] = make_float2(0.f, 0.f);               // slots 0..63 zero

            float prev = __shfl_up_sync(0xffffffffu, a.y, 1);
            if (lane == 0) prev = 0.f;                       // slot 64 zero
            dst[32 + lane] = make_float2(prev, a.x);         // slots 64..127

            float o63 = __shfl_sync(0xffffffffu, a.y, 31);
            if (lane == 0) {
                float sc = (tz == 2) ? 0.f : s_last * bh;    // slot 129
                dst[64] = make_float2(o63, sc);              // slots 128,129
            }

            if (tz < 2) {
                // companion scalar-only head h+4: all zero except slot 65
                float2* dst2 = out2 + g * 520 + (h + 4) * 65;
                float sc2 = (tz == 0 ? s_last : s_mid) * bh4;
                dst2[lane] = make_float2(0.f, 0.f);
                dst2[32 + lane] = make_float2(0.f, (lane == 0) ? sc2 : 0.f);
                if (lane == 0) dst2[64] = make_float2(0.f, 0.f);
            }
        }
    }
}

extern "C" void kernel_launch(void* const* d_in, const int* in_sizes, int n_in,
                              void* d_out, int out_size) {
    const float* x  = (const float*)d_in[0];
    const float* Mq = (const float*)d_in[1];
    const float* Bq = (const float*)d_in[2];
    const float* Mk = (const float*)d_in[3];
    const float* Bk = (const float*)d_in[4];
    const float* Mv = (const float*)d_in[5];
    float* out = (float*)d_out;

    const int tokens = in_sizes[0] / 130;       // B*N = 32768
    transpose_kernel<<<16, 256>>>(Mq, Mk, Mv);
    dim3 grid(tokens / TOK, 3);
    qkv_kernel<<<grid, 256>>>(x, Bq, Bk, out);
}

// round 4
// speedup vs baseline: 2.2833x; 2.2833x over previous
#include <cuda_runtime.h>

// ============================================================================
// CustomLinear fused q/k/v projection
//   x: (8, 4096, 130) fp32; per token:
//     x1 = x[0:64], s_mid = x[64], x2 = x[65:129], s_last = x[129]
//   q head h<4:  e[65:129] = M_q[h] @ x2 ; e[129] = s_last*bq[h]
//   q head h>=4: e[65]     = s_last*bq[h]
//   k head h<4:  e[65:129] = M_k[h] @ x1 ; e[129] = s_last*bk[h]
//   k head h>=4: e[65]     = s_mid *bk[h]
//   v all h:     e[65:129] = M_v[h] @ x1
//   out = concat(q, k, v), each (8, 4096, 8*130) fp32
// ============================================================================

#define TOK 32   // tokens per CTA
#define TG  8    // tokens per register accumulation group

// Transposed weights: g_MT[m][j*64 + i] = M_m[i][j], m = 0..3 Mq, 4..7 Mk, 8..15 Mv
__device__ __align__(16) float g_MT[16 * 4096];

__global__ void transpose_kernel(const float* __restrict__ Mq,
                                 const float* __restrict__ Mk,
                                 const float* __restrict__ Mv) {
    int m = blockIdx.x;  // 0..15
    const float* src = (m < 4) ? (Mq + m * 4096)
                     : (m < 8) ? (Mk + (m - 4) * 4096)
                               : (Mv + (m - 8) * 4096);
    float* dst = g_MT + m * 4096;
    for (int idx = threadIdx.x; idx < 4096; idx += blockDim.x) {
        int i = idx >> 6, j = idx & 63;
        dst[j * 64 + i] = src[idx];
    }
}

__global__ void __launch_bounds__(256, 3) qkv_kernel(
    const float* __restrict__ x,
    const float* __restrict__ Bq,
    const float* __restrict__ Bk,
    float* __restrict__ out)
{
    __shared__ __align__(16) float xsl[TOK * 64];  // per-token 64-float input slice
    __shared__ float2 xs[TOK];                     // {s_mid, s_last}

    const int  tz = blockIdx.y;                 // 0 = q, 1 = k, 2 = v
    const long g0 = (long)blockIdx.x * TOK;     // first global token of this CTA
    const int  slice_off = (tz == 0) ? 65 : 0;  // q reads x2, k/v read x1

    // Stage x slice for TOK tokens (coalesced 64-float runs per token)
    for (int idx = threadIdx.x; idx < TOK * 64; idx += 256) {
        int t = idx >> 6, j = idx & 63;
        xsl[idx] = x[(g0 + t) * 130 + slice_off + j];
    }
    if (threadIdx.x < TOK) {
        int t = threadIdx.x;
        xs[t] = make_float2(x[(g0 + t) * 130 + 64], x[(g0 + t) * 130 + 129]);
    }
    __syncthreads();

    const int w    = threadIdx.x >> 5;
    const int lane = threadIdx.x & 31;
    // out regions: q | k | v, each 8*4096*1040 floats = 17,039,360 float2
    float2* out2 = (float2*)out + (long)tz * 17039360L;

    int h, ngroup, t0_base;
    const float* MT;
    float bh = 0.f, bh4 = 0.f;
    if (tz < 2) {
        h = w >> 1;                       // matvec head 0..3
        int sub = w & 1;
        ngroup = 2;                       // 2 groups of 8 tokens
        t0_base = sub * 16;
        MT = g_MT + ((tz ? 4 : 0) + h) * 4096;
        const float* Bv = tz ? Bk : Bq;
        bh  = Bv[h];
        bh4 = Bv[h + 4];
    } else {
        h = w;                            // v: warp = head, 4 groups of 8 tokens
        ngroup = 4;
        t0_base = 0;
        MT = g_MT + (8 + h) * 4096;
    }

    for (int grp = 0; grp < ngroup; grp++) {
        const int t0 = t0_base + grp * TG;

        // lane computes outputs i = 2*lane, 2*lane+1 for TG tokens
        float acc0[TG], acc1[TG];
        #pragma unroll
        for (int t = 0; t < TG; t++) { acc0[t] = 0.f; acc1[t] = 0.f; }

        #pragma unroll
        for (int jc = 0; jc < 4; jc++) {
            // register-cache M^T chunk: 16 j's x 2 outputs (L1-resident, reused by TG tokens)
            float2 m[16];
            #pragma unroll
            for (int jj = 0; jj < 16; jj++)
                m[jj] = __ldg((const float2*)(MT + (jc * 16 + jj) * 64) + lane);

            #pragma unroll
            for (int t = 0; t < TG; t++) {
                const float* xr = xsl + (t0 + t) * 64 + jc * 16;
                #pragma unroll
                for (int jj = 0; jj < 16; jj += 4) {
                    float4 xv = *(const float4*)(xr + jj);   // broadcast LDS.128
                    acc0[t] = fmaf(m[jj    ].x, xv.x, acc0[t]);
                    acc1[t] = fmaf(m[jj    ].y, xv.x, acc1[t]);
                    acc0[t] = fmaf(m[jj + 1].x, xv.y, acc0[t]);
                    acc1[t] = fmaf(m[jj + 1].y, xv.y, acc1[t]);
                    acc0[t] = fmaf(m[jj + 2].x, xv.z, acc0[t]);
                    acc1[t] = fmaf(m[jj + 2].y, xv.z, acc1[t]);
                    acc0[t] = fmaf(m[jj + 3].x, xv.w, acc0[t]);
                    acc1[t] = fmaf(m[jj + 3].y, xv.w, acc1[t]);
                }
            }
        }

        // Write the full 130-float head block(s) as aligned float2 pairs.
        // Pair p covers slots (2p, 2p+1); payload lives at slots 65..129, so
        // pair 32+l = {out[2l-1], out[2l]} via shfl_up.
        #pragma unroll
        for (int t = 0; t < TG; t++) {
            long   g     = g0 + t0 + t;
            float2* dst  = out2 + g * 520 + h * 65;
            float  s_mid = xs[t0 + t].x, s_last = xs[t0 + t].y;

            dst[lane] = make_float2(0.f, 0.f);               // slots 0..63 zero

            float prev = __shfl_up_sync(0xffffffffu, acc1[t], 1);
            if (lane == 0) prev = 0.f;                       // slot 64 zero
            dst[32 + lane] = make_float2(prev, acc0[t]);     // slots 64..127

            float o63 = __shfl_sync(0xffffffffu, acc1[t], 31);
            if (lane == 0) {
                float sc = (tz == 2) ? 0.f : s_last * bh;    // slot 129
                dst[64] = make_float2(o63, sc);              // slots 128,129
            }

            if (tz < 2) {
                // companion scalar-only head h+4: all zero except slot 65
                float2* dst2 = out2 + g * 520 + (h + 4) * 65;
                float sc2 = (tz == 0 ? s_last : s_mid) * bh4;
                dst2[lane] = make_float2(0.f, 0.f);
                dst2[32 + lane] = make_float2(0.f, (lane == 0) ? sc2 : 0.f);
                if (lane == 0) dst2[64] = make_float2(0.f, 0.f);
            }
        }
    }
}

extern "C" void kernel_launch(void* const* d_in, const int* in_sizes, int n_in,
                              void* d_out, int out_size) {
    const float* x  = (const float*)d_in[0];
    const float* Mq = (const float*)d_in[1];
    const float* Bq = (const float*)d_in[2];
    const float* Mk = (const float*)d_in[3];
    const float* Bk = (const float*)d_in[4];
    const float* Mv = (const float*)d_in[5];
    float* out = (float*)d_out;

    const int tokens = in_sizes[0] / 130;       // B*N = 32768
    transpose_kernel<<<16, 256>>>(Mq, Mk, Mv);
    dim3 grid(tokens / TOK, 3);
    qkv_kernel<<<grid, 256>>>(x, Bq, Bk, out);
}